// round 4
// baseline (speedup 1.0000x reference)
#include <cuda_runtime.h>
#include <cuda_bf16.h>
#include <math.h>

#define HE 361
#define WE 720
#define LL 37
#define HM 180
#define WM 360
#define KK 32
#define NP 37
#define EPSV 1e-8f

#define XT 8                      // warps (= x positions) per block
#define NTHREADS 256
#define RAWN 148                  // 2 rows x 74 contiguous floats per var

#define OFF_PM  10368000L
#define OFF_PS  12441600L

__device__ __forceinline__ int ss_right_sh(const float* g, int n, float v) {
    int lo = 0, hi = n;
    while (lo < hi) {
        int m = (lo + hi) >> 1;
        if (g[m] <= v) lo = m + 1; else hi = m;
    }
    return lo;
}

// clip(searchsorted(grid, pt, 'right')-1, 0, n-2) via guess + fixup (grid ~linspace)
__device__ __forceinline__ int axis_idx(const float* __restrict__ grid, int n, float pt) {
    float g0 = __ldg(grid);
    float gN = __ldg(grid + n - 1);
    int i = (int)((pt - g0) / (gN - g0) * (float)(n - 1));
    i = min(max(i, 0), n - 2);
    while (i < n - 2 && __ldg(grid + i + 1) <= pt) i++;
    while (i > 0 && __ldg(grid + i) > pt) i--;
    return i;
}

__global__ __launch_bounds__(NTHREADS)
void era5_fused_kernel(const float* __restrict__ u,
                       const float* __restrict__ v,
                       const float* __restrict__ w,
                       const float* __restrict__ T,
                       const float* __restrict__ q,
                       const float* __restrict__ ps,
                       const float* __restrict__ era5_lat,
                       const float* __restrict__ era5_lon,
                       const float* __restrict__ model_lat,
                       const float* __restrict__ model_lon,
                       const float* __restrict__ p_levels,
                       const float* __restrict__ a_k,
                       const float* __restrict__ b_k,
                       float* __restrict__ out) {
    __shared__ float s_raw[XT][5 * RAWN];   // staging; reused for output staging
    __shared__ float s_hd[XT][5 * LL];      // horizontally-interped [v][l]
    __shared__ float s_lpe[NP];
    __shared__ float s_pl[NP];
    __shared__ float s_ak[KK], s_bk[KK];
    __shared__ int   s_ix[XT];
    __shared__ float s_tx[XT];
    __shared__ int   s_iy;
    __shared__ float s_ty;

    const int tid  = threadIdx.x;
    const int wrp  = tid >> 5;
    const int lane = tid & 31;
    const int y  = blockIdx.y;
    const int x0 = blockIdx.x * XT;

    // ---- phase 0: tables ----
    if (tid < XT) {
        float pt = __ldg(model_lon + x0 + tid);
        int i = axis_idx(era5_lon, WE, pt);
        s_ix[tid] = i;
        s_tx[tid] = (pt - __ldg(era5_lon + i)) / (__ldg(era5_lon + i + 1) - __ldg(era5_lon + i));
    } else if (tid == 32) {
        float pt = __ldg(model_lat + y);
        int i = axis_idx(era5_lat, HE, pt);
        s_iy = i;
        s_ty = (pt - __ldg(era5_lat + i)) / (__ldg(era5_lat + i + 1) - __ldg(era5_lat + i));
    }
    if (tid >= 64 && tid < 64 + NP) {
        float pl = __ldg(p_levels + tid - 64);
        s_pl[tid - 64]  = pl;
        s_lpe[tid - 64] = logf(pl + EPSV);
    }
    if (tid >= 128 && tid < 128 + KK) {
        s_ak[tid - 128] = __ldg(a_k + tid - 128);
        s_bk[tid - 128] = __ldg(b_k + tid - 128);
    }
    __syncthreads();

    const int   iy = s_iy;
    const float ty = s_ty;
    const int   ix = s_ix[wrp];
    const float tx = s_tx[wrp];
    const int   x  = x0 + wrp;

    const float w00 = (1.f - ty) * (1.f - tx);
    const float w01 = (1.f - ty) * tx;
    const float w10 = ty * (1.f - tx);
    const float w11 = ty * tx;

    const int base00 = (iy * WE + ix) * LL;          // 74 contiguous floats (2 columns)
    const int base10 = base00 + WE * LL;

    // ---- phase 1: coalesced staged loads, all 5 vars in flight ----
    const float* __restrict__ ptrs[5] = { u, v, w, T, q };
    float* sw = s_raw[wrp];
    #pragma unroll
    for (int vv = 0; vv < 5; vv++) {
        const float* __restrict__ a = ptrs[vv];
        #pragma unroll
        for (int i = lane; i < 74; i += 32) {
            sw[vv * RAWN + i]      = __ldg(a + base00 + i);
            sw[vv * RAWN + 74 + i] = __ldg(a + base10 + i);
        }
    }
    // surface pressure (warp-uniform broadcast loads)
    const int pbase = iy * WE + ix;
    float psm = w00 * __ldg(ps + pbase)      + w01 * __ldg(ps + pbase + 1)
              + w10 * __ldg(ps + pbase + WE) + w11 * __ldg(ps + pbase + WE + 1);
    __syncwarp();

    // ---- horizontal bilinear from shared ----
    float* shd = s_hd[wrp];
    #pragma unroll
    for (int vv = 0; vv < 5; vv++) {
        const float* r = sw + vv * RAWN;
        #pragma unroll
        for (int l = lane; l < LL; l += 32) {
            shd[vv * LL + l] = w00 * r[l] + w01 * r[l + LL]
                             + w10 * r[74 + l] + w11 * r[74 + LL + l];
        }
    }
    __syncwarp();

    // ---- phase 2: vertical interp (k = lane) ----
    const int k = lane;
    int nv = ss_right_sh(s_pl, NP, psm);
    bool valid = (nv >= 2);

    float p  = s_ak[k] + s_bk[k] * psm;
    float lp = logf(p + EPSV);

    int idx = ss_right_sh(s_lpe, NP, lp) - 1;
    idx = min(max(idx, 0), max(nv - 2, 0));

    float lx0 = s_lpe[idx];
    float lx1 = s_lpe[idx + 1];
    float t   = (lp - lx0) / (lx1 - lx0);

    float res[5];
    #pragma unroll
    for (int vi = 0; vi < 5; vi++) {
        float g0 = shd[vi * LL + idx];
        float g1 = shd[vi * LL + idx + 1];
        float o  = g0 + t * (g1 - g0);
        if (!valid) o = 0.f;            // mask BEFORE clip (matches reference)
        res[vi] = o;
    }
    res[3] = fminf(fmaxf(res[3], 150.f), 350.f);
    res[4] = fminf(fmaxf(res[4], 0.f), 0.05f);

    // ---- coalesced output via shared transpose (reuse s_raw) ----
    __syncwarp();
    #pragma unroll
    for (int vi = 0; vi < 5; vi++)
        sw[k * 5 + vi] = res[vi];
    __syncwarp();

    const long cell   = (long)(y * WM + x);
    const long obase  = cell * 160;     // 160 floats = 640B = 5 aligned lines
    #pragma unroll
    for (int i = lane; i < 160; i += 32)
        out[obase + i] = sw[i];

    out[OFF_PM + cell * KK + k] = p;
    if (k == 0)
        out[OFF_PS + cell] = fminf(fmaxf(psm, 30000.f), 110000.f);
}

extern "C" void kernel_launch(void* const* d_in, const int* in_sizes, int n_in,
                              void* d_out, int out_size) {
    const float* u         = (const float*)d_in[0];
    const float* v         = (const float*)d_in[1];
    const float* w         = (const float*)d_in[2];
    const float* T         = (const float*)d_in[3];
    const float* q         = (const float*)d_in[4];
    const float* ps        = (const float*)d_in[5];
    const float* era5_lat  = (const float*)d_in[6];
    const float* era5_lon  = (const float*)d_in[7];
    const float* model_lat = (const float*)d_in[8];
    const float* model_lon = (const float*)d_in[9];
    const float* p_levels  = (const float*)d_in[10];
    const float* a_k       = (const float*)d_in[11];
    const float* b_k       = (const float*)d_in[12];
    float* out = (float*)d_out;

    dim3 block(NTHREADS);
    dim3 grid(WM / XT, HM);
    era5_fused_kernel<<<grid, block>>>(u, v, w, T, q, ps,
                                       era5_lat, era5_lon, model_lat, model_lon,
                                       p_levels, a_k, b_k, out);
}

// round 5
// speedup vs baseline: 1.1048x; 1.1048x over previous
#include <cuda_runtime.h>
#include <cuda_bf16.h>
#include <math.h>

#define HE 361
#define WE 720
#define LL 37
#define HM 180
#define WM 360
#define KK 32
#define NP 37
#define EPSV 1e-8f

#define XT 8                      // x positions per block
#define NTHREADS 256

#define OFF_PM  10368000L
#define OFF_PS  12441600L

__device__ __forceinline__ int ss_right_sh(const float* g, int n, float v) {
    // searchsorted(side='right'): first index m with g[m] > v
    int lo = 0, hi = n;
    while (lo < hi) {
        int m = (lo + hi) >> 1;
        if (g[m] <= v) lo = m + 1; else hi = m;
    }
    return lo;
}

// clip(searchsorted(grid, pt, 'right')-1, 0, n-2) via linear guess + fixup
__device__ __forceinline__ int axis_idx(const float* __restrict__ grid, int n, float pt) {
    float g0 = __ldg(grid);
    float gN = __ldg(grid + n - 1);
    int i = (int)((pt - g0) / (gN - g0) * (float)(n - 1));
    i = min(max(i, 0), n - 2);
    while (i < n - 2 && __ldg(grid + i + 1) <= pt) i++;
    while (i > 0 && __ldg(grid + i) > pt) i--;
    return i;
}

__global__ __launch_bounds__(NTHREADS, 4)
void era5_fused_kernel(const float* __restrict__ u,
                       const float* __restrict__ v,
                       const float* __restrict__ w,
                       const float* __restrict__ T,
                       const float* __restrict__ q,
                       const float* __restrict__ ps,
                       const float* __restrict__ era5_lat,
                       const float* __restrict__ era5_lon,
                       const float* __restrict__ model_lat,
                       const float* __restrict__ model_lon,
                       const float* __restrict__ p_levels,
                       const float* __restrict__ a_k,
                       const float* __restrict__ b_k,
                       float* __restrict__ out) {
    __shared__ float s_lpe[NP];
    __shared__ float s_pl[NP];
    __shared__ float s_ak[KK], s_bk[KK];
    __shared__ int   s_ix[XT];
    __shared__ float s_tx[XT];
    __shared__ int   s_iy;
    __shared__ float s_ty;

    const int tid = threadIdx.y * KK + threadIdx.x;
    const int y  = blockIdx.y;
    const int x0 = blockIdx.x * XT;

    // ---- inline prologue: axis + constant tables ----
    if (tid < XT) {
        float pt = __ldg(model_lon + x0 + tid);
        int i = axis_idx(era5_lon, WE, pt);
        s_ix[tid] = i;
        s_tx[tid] = (pt - __ldg(era5_lon + i)) / (__ldg(era5_lon + i + 1) - __ldg(era5_lon + i));
    } else if (tid == 32) {
        float pt = __ldg(model_lat + y);
        int i = axis_idx(era5_lat, HE, pt);
        s_iy = i;
        s_ty = (pt - __ldg(era5_lat + i)) / (__ldg(era5_lat + i + 1) - __ldg(era5_lat + i));
    }
    if (tid >= 64 && tid < 64 + NP) {
        float pl = __ldg(p_levels + tid - 64);
        s_pl[tid - 64]  = pl;
        s_lpe[tid - 64] = logf(pl + EPSV);
    }
    if (tid >= 128 && tid < 128 + KK) {
        s_ak[tid - 128] = __ldg(a_k + tid - 128);
        s_bk[tid - 128] = __ldg(b_k + tid - 128);
    }
    __syncthreads();

    const int k  = threadIdx.x;              // model level 0..31
    const int xl = threadIdx.y;              // 0..7
    const int x  = x0 + xl;

    const int   iy = s_iy;   const float ty = s_ty;
    const int   ix = s_ix[xl]; const float tx = s_tx[xl];

    const float w00 = (1.f - ty) * (1.f - tx);
    const float w01 = (1.f - ty) * tx;
    const float w10 = ty * (1.f - tx);
    const float w11 = ty * tx;

    const int p00 = iy * WE + ix;
    const int p01 = p00 + 1;
    const int p10 = p00 + WE;
    const int p11 = p10 + 1;

    // surface pressure bilinear (warp-uniform broadcast loads)
    const float psm = w00 * __ldg(ps + p00) + w01 * __ldg(ps + p01)
                    + w10 * __ldg(ps + p10) + w11 * __ldg(ps + p11);

    const int nv = ss_right_sh(s_pl, NP, psm);
    const bool valid = (nv >= 2);

    const float p  = s_ak[k] + s_bk[k] * psm;
    const float lp = logf(p + EPSV);

    int idx = ss_right_sh(s_lpe, NP, lp) - 1;
    idx = min(max(idx, 0), max(nv - 2, 0));

    const float lx0 = s_lpe[idx];
    const float lx1 = s_lpe[idx + 1];
    const float t   = (lp - lx0) / (lx1 - lx0);

    const int c00 = p00 * LL + idx;
    const int c01 = p01 * LL + idx;
    const int c10 = p10 * LL + idx;
    const int c11 = p11 * LL + idx;

    const float* __restrict__ ptrs[5] = { u, v, w, T, q };

    // ---- batch 1: all 20 g0 corner loads in flight ----
    float e00[5], e01[5], e10[5], e11[5];
    #pragma unroll
    for (int vi = 0; vi < 5; vi++) {
        const float* __restrict__ a = ptrs[vi];
        e00[vi] = __ldg(a + c00);
        e01[vi] = __ldg(a + c01);
        e10[vi] = __ldg(a + c10);
        e11[vi] = __ldg(a + c11);
    }
    float g0[5];
    #pragma unroll
    for (int vi = 0; vi < 5; vi++)
        g0[vi] = w00 * e00[vi] + w01 * e01[vi] + w10 * e10[vi] + w11 * e11[vi];

    // ---- batch 2: all 20 g1 loads (idx+1 -> mostly L1 hits) ----
    float f00[5], f01[5], f10[5], f11[5];
    #pragma unroll
    for (int vi = 0; vi < 5; vi++) {
        const float* __restrict__ a = ptrs[vi];
        f00[vi] = __ldg(a + c00 + 1);
        f01[vi] = __ldg(a + c01 + 1);
        f10[vi] = __ldg(a + c10 + 1);
        f11[vi] = __ldg(a + c11 + 1);
    }

    const long cell  = (long)(y * WM + x);
    const long obase = (cell * KK + k) * 5;

    float res[5];
    #pragma unroll
    for (int vi = 0; vi < 5; vi++) {
        float g1 = w00 * f00[vi] + w01 * f01[vi] + w10 * f10[vi] + w11 * f11[vi];
        float o  = g0[vi] + t * (g1 - g0[vi]);
        if (!valid) o = 0.f;              // mask BEFORE clip (matches reference)
        res[vi] = o;
    }
    res[3] = fminf(fmaxf(res[3], 150.f), 350.f);
    res[4] = fminf(fmaxf(res[4], 0.f), 0.05f);

    #pragma unroll
    for (int vi = 0; vi < 5; vi++)
        out[obase + vi] = res[vi];

    out[OFF_PM + cell * KK + k] = p;
    if (k == 0)
        out[OFF_PS + cell] = fminf(fmaxf(psm, 30000.f), 110000.f);
}

extern "C" void kernel_launch(void* const* d_in, const int* in_sizes, int n_in,
                              void* d_out, int out_size) {
    const float* u         = (const float*)d_in[0];
    const float* v         = (const float*)d_in[1];
    const float* w         = (const float*)d_in[2];
    const float* T         = (const float*)d_in[3];
    const float* q         = (const float*)d_in[4];
    const float* ps        = (const float*)d_in[5];
    const float* era5_lat  = (const float*)d_in[6];
    const float* era5_lon  = (const float*)d_in[7];
    const float* model_lat = (const float*)d_in[8];
    const float* model_lon = (const float*)d_in[9];
    const float* p_levels  = (const float*)d_in[10];
    const float* a_k       = (const float*)d_in[11];
    const float* b_k       = (const float*)d_in[12];
    float* out = (float*)d_out;

    dim3 block(KK, XT);
    dim3 grid(WM / XT, HM);
    era5_fused_kernel<<<grid, block>>>(u, v, w, T, q, ps,
                                       era5_lat, era5_lon, model_lat, model_lon,
                                       p_levels, a_k, b_k, out);
}

// round 7
// speedup vs baseline: 1.1872x; 1.0745x over previous
#include <cuda_runtime.h>
#include <cuda_bf16.h>
#include <math.h>

#define HE 361
#define WE 720
#define LL 37
#define HM 180
#define WM 360
#define KK 32
#define NP 37
#define EPSV 1e-8f

#define XT 8                      // x positions (warps) per block
#define NTHREADS 256

#define OFF_PM  10368000L
#define OFF_PS  12441600L

__device__ __forceinline__ int ss_right_sh(const float* g, int n, float v) {
    // searchsorted(side='right'): first index m with g[m] > v
    int lo = 0, hi = n;
    while (lo < hi) {
        int m = (lo + hi) >> 1;
        if (g[m] <= v) lo = m + 1; else hi = m;
    }
    return lo;
}

// clip(searchsorted(grid, pt, 'right')-1, 0, n-2) via linear guess + fixup
__device__ __forceinline__ int axis_idx(const float* __restrict__ grid, int n, float pt) {
    float g0 = __ldg(grid);
    float gN = __ldg(grid + n - 1);
    int i = (int)((pt - g0) / (gN - g0) * (float)(n - 1));
    i = min(max(i, 0), n - 2);
    while (i < n - 2 && __ldg(grid + i + 1) <= pt) i++;
    while (i > 0 && __ldg(grid + i) > pt) i--;
    return i;
}

__global__ __launch_bounds__(NTHREADS)
void era5_fused_kernel(const float* __restrict__ u,
                       const float* __restrict__ v,
                       const float* __restrict__ w,
                       const float* __restrict__ T,
                       const float* __restrict__ q,
                       const float* __restrict__ ps,
                       const float* __restrict__ era5_lat,
                       const float* __restrict__ era5_lon,
                       const float* __restrict__ model_lat,
                       const float* __restrict__ model_lon,
                       const float* __restrict__ p_levels,
                       const float* __restrict__ a_k,
                       const float* __restrict__ b_k,
                       float* __restrict__ out) {
    __shared__ float s_lpe[NP];
    __shared__ float s_pl[NP];
    __shared__ float s_ak[KK], s_bk[KK];
    __shared__ int   s_ix[XT];
    __shared__ float s_tx[XT];
    __shared__ int   s_iy;
    __shared__ float s_ty;
    __shared__ float s_out[XT][KK * 5];   // per-warp output staging (stride-5 writes, gcd(5,32)=1)

    const int tid = threadIdx.y * KK + threadIdx.x;
    const int y  = blockIdx.y;
    const int x0 = blockIdx.x * XT;

    // ---- inline prologue: axis + constant tables ----
    if (tid < XT) {
        float pt = __ldg(model_lon + x0 + tid);
        int i = axis_idx(era5_lon, WE, pt);
        s_ix[tid] = i;
        s_tx[tid] = (pt - __ldg(era5_lon + i)) / (__ldg(era5_lon + i + 1) - __ldg(era5_lon + i));
    } else if (tid == 32) {
        float pt = __ldg(model_lat + y);
        int i = axis_idx(era5_lat, HE, pt);
        s_iy = i;
        s_ty = (pt - __ldg(era5_lat + i)) / (__ldg(era5_lat + i + 1) - __ldg(era5_lat + i));
    }
    if (tid >= 64 && tid < 64 + NP) {
        float pl = __ldg(p_levels + tid - 64);
        s_pl[tid - 64]  = pl;
        s_lpe[tid - 64] = logf(pl + EPSV);
    }
    if (tid >= 128 && tid < 128 + KK) {
        s_ak[tid - 128] = __ldg(a_k + tid - 128);
        s_bk[tid - 128] = __ldg(b_k + tid - 128);
    }
    __syncthreads();

    const int k  = threadIdx.x;              // model level 0..31 (= lane)
    const int xl = threadIdx.y;              // warp id 0..7
    const int x  = x0 + xl;

    const int   iy = s_iy;     const float ty = s_ty;
    const int   ix = s_ix[xl]; const float tx = s_tx[xl];

    const float w00 = (1.f - ty) * (1.f - tx);
    const float w01 = (1.f - ty) * tx;
    const float w10 = ty * (1.f - tx);
    const float w11 = ty * tx;

    const int p00 = iy * WE + ix;
    const int p01 = p00 + 1;
    const int p10 = p00 + WE;
    const int p11 = p10 + 1;

    // surface pressure bilinear (warp-uniform broadcast loads)
    const float psm = w00 * __ldg(ps + p00) + w01 * __ldg(ps + p01)
                    + w10 * __ldg(ps + p10) + w11 * __ldg(ps + p11);

    const int nv = ss_right_sh(s_pl, NP, psm);
    const bool valid = (nv >= 2);

    const float p  = s_ak[k] + s_bk[k] * psm;
    const float lp = logf(p + EPSV);

    int idx = ss_right_sh(s_lpe, NP, lp) - 1;
    idx = min(max(idx, 0), max(nv - 2, 0));

    const float lx0 = s_lpe[idx];
    const float lx1 = s_lpe[idx + 1];
    const float t   = (lp - lx0) / (lx1 - lx0);

    const int c00 = p00 * LL + idx;
    const int c01 = p01 * LL + idx;
    const int c10 = p10 * LL + idx;
    const int c11 = p11 * LL + idx;

    const float* __restrict__ ptrs[5] = { u, v, w, T, q };
    float res[5];
    #pragma unroll
    for (int vi = 0; vi < 5; vi++) {
        const float* __restrict__ a = ptrs[vi];
        float g0 = w00 * __ldg(a + c00)     + w01 * __ldg(a + c01)
                 + w10 * __ldg(a + c10)     + w11 * __ldg(a + c11);
        float g1 = w00 * __ldg(a + c00 + 1) + w01 * __ldg(a + c01 + 1)
                 + w10 * __ldg(a + c10 + 1) + w11 * __ldg(a + c11 + 1);
        float o = g0 + t * (g1 - g0);
        if (!valid) o = 0.f;              // mask BEFORE clip (matches reference)
        res[vi] = o;
    }
    res[3] = fminf(fmaxf(res[3], 150.f), 350.f);
    res[4] = fminf(fmaxf(res[4], 0.f), 0.05f);

    // ---- coalesced out3d via per-warp shared transpose ----
    #pragma unroll
    for (int vi = 0; vi < 5; vi++)
        s_out[xl][k * 5 + vi] = res[vi];
    __syncwarp();

    const long cell  = (long)(y * WM + x);
    const long obase = cell * (KK * 5);     // 160 floats = 640B = 5 aligned 128B lines
    #pragma unroll
    for (int i = 0; i < 5; i++)
        out[obase + i * KK + k] = s_out[xl][i * KK + k];

    out[OFF_PM + cell * KK + k] = p;
    if (k == 0)
        out[OFF_PS + cell] = fminf(fmaxf(psm, 30000.f), 110000.f);
}

extern "C" void kernel_launch(void* const* d_in, const int* in_sizes, int n_in,
                              void* d_out, int out_size) {
    const float* u         = (const float*)d_in[0];
    const float* v         = (const float*)d_in[1];
    const float* w         = (const float*)d_in[2];
    const float* T         = (const float*)d_in[3];
    const float* q         = (const float*)d_in[4];
    const float* ps        = (const float*)d_in[5];
    const float* era5_lat  = (const float*)d_in[6];
    const float* era5_lon  = (const float*)d_in[7];
    const float* model_lat = (const float*)d_in[8];
    const float* model_lon = (const float*)d_in[9];
    const float* p_levels  = (const float*)d_in[10];
    const float* a_k       = (const float*)d_in[11];
    const float* b_k       = (const float*)d_in[12];
    float* out = (float*)d_out;

    dim3 block(KK, XT);
    dim3 grid(WM / XT, HM);
    era5_fused_kernel<<<grid, block>>>(u, v, w, T, q, ps,
                                       era5_lat, era5_lon, model_lat, model_lon,
                                       p_levels, a_k, b_k, out);
}

// round 8
// speedup vs baseline: 1.3810x; 1.1633x over previous
#include <cuda_runtime.h>
#include <cuda_bf16.h>
#include <math.h>

#define HE 361
#define WE 720
#define LL 37
#define HM 180
#define WM 360
#define KK 32
#define NP 37
#define EPSV 1e-8f

#define XT 8                      // x positions (warps) per block
#define NTHREADS 256

#define OFF_PM  10368000L
#define OFF_PS  12441600L

__device__ __forceinline__ int ss_right_sh(const float* g, int n, float v) {
    // searchsorted(side='right'): first index m with g[m] > v
    int lo = 0, hi = n;
    while (lo < hi) {
        int m = (lo + hi) >> 1;
        if (g[m] <= v) lo = m + 1; else hi = m;
    }
    return lo;
}

// clip(searchsorted(grid, pt, 'right')-1, 0, n-2) via linear guess + fixup
__device__ __forceinline__ int axis_idx(const float* __restrict__ grid, int n, float pt) {
    float g0 = __ldg(grid);
    float gN = __ldg(grid + n - 1);
    int i = (int)((pt - g0) / (gN - g0) * (float)(n - 1));
    i = min(max(i, 0), n - 2);
    while (i < n - 2 && __ldg(grid + i + 1) <= pt) i++;
    while (i > 0 && __ldg(grid + i) > pt) i--;
    return i;
}

__device__ __forceinline__ void pf_l1(const float* p) {
    asm volatile("prefetch.global.L1 [%0];" :: "l"(p));
}

__global__ __launch_bounds__(NTHREADS)
void era5_fused_kernel(const float* __restrict__ u,
                       const float* __restrict__ v,
                       const float* __restrict__ w,
                       const float* __restrict__ T,
                       const float* __restrict__ q,
                       const float* __restrict__ ps,
                       const float* __restrict__ era5_lat,
                       const float* __restrict__ era5_lon,
                       const float* __restrict__ model_lat,
                       const float* __restrict__ model_lon,
                       const float* __restrict__ p_levels,
                       const float* __restrict__ a_k,
                       const float* __restrict__ b_k,
                       float* __restrict__ out) {
    __shared__ float s_lpe[NP];
    __shared__ float s_pl[NP];
    __shared__ float s_ak[KK], s_bk[KK];
    __shared__ int   s_ix[XT];
    __shared__ float s_tx[XT];
    __shared__ int   s_iy;
    __shared__ float s_ty;
    __shared__ float s_out[XT][KK * 5];   // per-warp output staging

    const int tid = threadIdx.y * KK + threadIdx.x;
    const int y  = blockIdx.y;
    const int x0 = blockIdx.x * XT;

    // ---- inline prologue: axis + constant tables ----
    if (tid < XT) {
        float pt = __ldg(model_lon + x0 + tid);
        int i = axis_idx(era5_lon, WE, pt);
        s_ix[tid] = i;
        s_tx[tid] = (pt - __ldg(era5_lon + i)) / (__ldg(era5_lon + i + 1) - __ldg(era5_lon + i));
    } else if (tid == 32) {
        float pt = __ldg(model_lat + y);
        int i = axis_idx(era5_lat, HE, pt);
        s_iy = i;
        s_ty = (pt - __ldg(era5_lat + i)) / (__ldg(era5_lat + i + 1) - __ldg(era5_lat + i));
    }
    if (tid >= 64 && tid < 64 + NP) {
        float pl = __ldg(p_levels + tid - 64);
        s_pl[tid - 64]  = pl;
        s_lpe[tid - 64] = logf(pl + EPSV);
    }
    if (tid >= 128 && tid < 128 + KK) {
        s_ak[tid - 128] = __ldg(a_k + tid - 128);
        s_bk[tid - 128] = __ldg(b_k + tid - 128);
    }
    __syncthreads();

    const int k  = threadIdx.x;              // model level 0..31 (= lane)
    const int xl = threadIdx.y;              // warp id 0..7
    const int x  = x0 + xl;

    const int   iy = s_iy;     const float ty = s_ty;
    const int   ix = s_ix[xl]; const float tx = s_tx[xl];

    const float w00 = (1.f - ty) * (1.f - tx);
    const float w01 = (1.f - ty) * tx;
    const float w10 = ty * (1.f - tx);
    const float w11 = ty * tx;

    const int p00 = iy * WE + ix;
    const int p01 = p00 + 1;
    const int p10 = p00 + WE;
    const int p11 = p10 + 1;

    const int base00 = p00 * LL;     // 74-float run covering columns c00,c01
    const int base10 = p10 * LL;     // 74-float run covering columns c10,c11

    // ---- fire-and-forget L1 prefetch of all 10 corner regions ----
    // 4 touches per 296B region (gaps < 128B -> every line hit), 2 regions x 5 vars.
    {
        const int tp  = k & 3;                        // touch id 0..3
        const int off = tp * 24 + ((tp & 1) & (tp >> 1)); // 0,24,48,73
        const int bb  = ((k >> 2) & 1) ? base10 : base00;
        const int vv  = k >> 3;                       // var 0..3 for lanes 0..31
        const float* a0 = (vv == 0) ? u : (vv == 1) ? v : (vv == 2) ? w : T;
        pf_l1(a0 + bb + off);
        if (k < 8)                                    // var 4 (q): lanes 0..7
            pf_l1(q + bb + off);
    }

    // surface pressure bilinear (warp-uniform broadcast loads)
    const float psm = w00 * __ldg(ps + p00) + w01 * __ldg(ps + p01)
                    + w10 * __ldg(ps + p10) + w11 * __ldg(ps + p11);

    const int nv = ss_right_sh(s_pl, NP, psm);
    const bool valid = (nv >= 2);

    const float p  = s_ak[k] + s_bk[k] * psm;
    const float lp = logf(p + EPSV);

    int idx = ss_right_sh(s_lpe, NP, lp) - 1;
    idx = min(max(idx, 0), max(nv - 2, 0));

    const float lx0 = s_lpe[idx];
    const float lx1 = s_lpe[idx + 1];
    const float t   = (lp - lx0) / (lx1 - lx0);

    const int c00 = base00 + idx;
    const int c01 = c00 + LL;
    const int c10 = base10 + idx;
    const int c11 = c10 + LL;

    const float* __restrict__ ptrs[5] = { u, v, w, T, q };
    float res[5];
    #pragma unroll
    for (int vi = 0; vi < 5; vi++) {
        const float* __restrict__ a = ptrs[vi];
        float g0 = w00 * __ldg(a + c00)     + w01 * __ldg(a + c01)
                 + w10 * __ldg(a + c10)     + w11 * __ldg(a + c11);
        float g1 = w00 * __ldg(a + c00 + 1) + w01 * __ldg(a + c01 + 1)
                 + w10 * __ldg(a + c10 + 1) + w11 * __ldg(a + c11 + 1);
        float o = g0 + t * (g1 - g0);
        if (!valid) o = 0.f;              // mask BEFORE clip (matches reference)
        res[vi] = o;
    }
    res[3] = fminf(fmaxf(res[3], 150.f), 350.f);
    res[4] = fminf(fmaxf(res[4], 0.f), 0.05f);

    // ---- coalesced out3d via per-warp shared transpose ----
    #pragma unroll
    for (int vi = 0; vi < 5; vi++)
        s_out[xl][k * 5 + vi] = res[vi];
    __syncwarp();

    const long cell  = (long)(y * WM + x);
    const long obase = cell * (KK * 5);     // 160 floats = 640B = 5 aligned 128B lines
    #pragma unroll
    for (int i = 0; i < 5; i++)
        out[obase + i * KK + k] = s_out[xl][i * KK + k];

    out[OFF_PM + cell * KK + k] = p;
    if (k == 0)
        out[OFF_PS + cell] = fminf(fmaxf(psm, 30000.f), 110000.f);
}

extern "C" void kernel_launch(void* const* d_in, const int* in_sizes, int n_in,
                              void* d_out, int out_size) {
    const float* u         = (const float*)d_in[0];
    const float* v         = (const float*)d_in[1];
    const float* w         = (const float*)d_in[2];
    const float* T         = (const float*)d_in[3];
    const float* q         = (const float*)d_in[4];
    const float* ps        = (const float*)d_in[5];
    const float* era5_lat  = (const float*)d_in[6];
    const float* era5_lon  = (const float*)d_in[7];
    const float* model_lat = (const float*)d_in[8];
    const float* model_lon = (const float*)d_in[9];
    const float* p_levels  = (const float*)d_in[10];
    const float* a_k       = (const float*)d_in[11];
    const float* b_k       = (const float*)d_in[12];
    float* out = (float*)d_out;

    dim3 block(KK, XT);
    dim3 grid(WM / XT, HM);
    era5_fused_kernel<<<grid, block>>>(u, v, w, T, q, ps,
                                       era5_lat, era5_lon, model_lat, model_lon,
                                       p_levels, a_k, b_k, out);
}